// round 15
// baseline (speedup 1.0000x reference)
#include <cuda_runtime.h>
#include <cuda_bf16.h>
#include <cstdint>
#include <cstddef>

#define DK 256        // feature dim
#define NC 32         // nodes per chunk (GEMM2 K)
#define ZS 74         // split-K CTAs per d-tile (x2 d-tiles = 148 CTAs)

// ---- smem layout (R8): W resident, single-buffered nodes/mask/yT ----
#define W_STRIDE  528                      // 256 bf16 + 8 pad
#define ND_STRIDE 528
#define MK_STRIDE 160                      // 32 int32 + 8 pad
#define YT_STRIDE 80                       // 32 bf16 + 8 pad
#define OFF_WT 0
#define OFF_WG 67584                       // 128*528
#define OFF_ND 135168                      // + 128*528
#define OFF_MK 152064                      // + 32*528
#define OFF_YT 193024                      // + 256*160
#define SMEM_TOTAL 203264                  // + 128*80

static __device__ __forceinline__ uint32_t smem_u32(const void* p) {
    uint32_t a;
    asm("{ .reg .u64 t; cvta.to.shared.u64 t, %1; cvt.u32.u64 %0, t; }" : "=r"(a) : "l"(p));
    return a;
}

#define LDSM_X4(R, addr)                                                      \
    asm volatile("ldmatrix.sync.aligned.m8n8.x4.shared.b16 {%0,%1,%2,%3}, [%4];" \
                 : "=r"((R)[0]), "=r"((R)[1]), "=r"((R)[2]), "=r"((R)[3])     \
                 : "r"(addr))

#define MMA_BF16(C, A, b0, b1)                                                \
    asm volatile("mma.sync.aligned.m16n8k16.row.col.f32.bf16.bf16.f32 "       \
                 "{%0,%1,%2,%3},{%4,%5,%6,%7},{%8,%9},{%0,%1,%2,%3};"         \
                 : "+f"((C)[0]), "+f"((C)[1]), "+f"((C)[2]), "+f"((C)[3])     \
                 : "r"((A)[0]), "r"((A)[1]), "r"((A)[2]), "r"((A)[3]),        \
                   "r"(b0), "r"(b1))

#define CP16(dst, src)                                                        \
    asm volatile("cp.async.cg.shared.global [%0], [%1], 16;"                  \
                 :: "r"(dst), "l"(src) : "memory")
#define CP_COMMIT() asm volatile("cp.async.commit_group;" ::: "memory")
#define CP_WAIT0()  asm volatile("cp.async.wait_group 0;" ::: "memory")

// mask int {0,1} pair -> packed bf16x2 {1.0 or 0.0}: exact, 2 IMADs
static __device__ __forceinline__ uint32_t cvtm(int2 v) {
    return (uint32_t)v.x * 0x3F80u + (uint32_t)v.y * 0x3F800000u;
}

static __device__ __forceinline__ uint2 pack_bf4(float4 v) {
    __nv_bfloat162 lo = __floats2bfloat162_rn(v.x, v.y);
    __nv_bfloat162 hi = __floats2bfloat162_rn(v.z, v.w);
    uint2 u;
    u.x = *reinterpret_cast<uint32_t*>(&lo);
    u.y = *reinterpret_cast<uint32_t*>(&hi);
    return u;
}

static __device__ __forceinline__ float sigm(float x) { return 1.0f / (1.0f + __expf(-x)); }

// ---------------------------------------------------------------------------
// R8 structure exactly (3 barriers, cp.async mask, reg-prefetched nodes).
// Single change: GEMM2 warp layout 16m x 1n -> 8m x 2n (warp 32b x 64d),
// halving the yT ldmatrix amplification (131 -> 66 KB/chunk).
// ---------------------------------------------------------------------------
__global__ __launch_bounds__(512, 1)
void fused_agg(const float* __restrict__ nodes, const int* __restrict__ mask,
               const float* __restrict__ Wt, const float* __restrict__ bt,
               const float* __restrict__ Wg, const float* __restrict__ bg,
               float* __restrict__ out, int Nn)
{
    extern __shared__ char sm[];
    const uint32_t sb = smem_u32(sm);
    const int tid  = threadIdx.x;
    const int lane = tid & 31;
    const int wid  = tid >> 5;
    const int g    = lane >> 2;
    const int tg   = lane & 3;
    const int z    = blockIdx.x;
    const int d0   = blockIdx.y * 128;

    // GEMM1 warp roles: 8 m-warps (16 d rows) x 2 n-warps (16 n cols)
    const int wm = wid & 7;
    const int wn = wid >> 3;
    // GEMM2 warp roles: 8 m-warps (32 b rows) x 2 n-warps (64 d cols)
    const int wm2 = wid >> 1;
    const int wn2 = wid & 1;

    // Per-thread gate biases for GEMM1 epilogue rows (d = wm*16+g, +8)
    const float bt0 = bt[d0 + wm * 16 + g];
    const float bt1 = bt[d0 + wm * 16 + 8 + g];
    const float bg0 = bg[d0 + wm * 16 + g];
    const float bg1 = bg[d0 + wm * 16 + 8 + g];

    // Persistent GEMM2 accumulators: 2 mf x 8 n8 x 4 = 64 regs
    float acc2[2][8][4];
    #pragma unroll
    for (int i = 0; i < 2; i++)
        #pragma unroll
        for (int j = 0; j < 8; j++)
            #pragma unroll
            for (int q = 0; q < 4; q++) acc2[i][j][q] = 0.f;

    const int NCHK = Nn / NC;

    // ---- prologue: issue cp.async for mask(chunk z) ----
    {
        const int n0 = z * NC;
        #pragma unroll
        for (int i = 0; i < 4; i++) {
            int o = tid + i * 512;            // 2048 ops: 256 rows x 8 segs
            int row = o >> 3, seg = o & 7;
            CP16(sb + OFF_MK + row * MK_STRIDE + seg * 16,
                 (const char*)(mask + (size_t)row * Nn + n0) + seg * 16);
        }
        CP_COMMIT();
    }

    // ---- stage resident W (both matrices, f32 -> bf16, padded rows) ----
    #pragma unroll
    for (int i = 0; i < 16; i++) {
        int f4  = tid + i * 512;              // 8192 float4 per matrix
        int row = f4 >> 6;
        int col = (f4 & 63) * 4;
        uint2 a = pack_bf4(*(const float4*)(Wt + (size_t)(d0 + row) * DK + col));
        uint2 b = pack_bf4(*(const float4*)(Wg + (size_t)(d0 + row) * DK + col));
        *(uint2*)(sm + OFF_WT + row * W_STRIDE + col * 2) = a;
        *(uint2*)(sm + OFF_WG + row * W_STRIDE + col * 2) = b;
    }

    // ldmatrix lane addresses
    const uint32_t aWt = sb + OFF_WT + (wm * 16 + (lane & 15)) * W_STRIDE + ((lane >> 4) << 4);
    const uint32_t aWg = aWt + (uint32_t)(OFF_WG - OFF_WT);
    const uint32_t bNd = sb + OFF_ND
                       + (wn * 16 + (lane & 7) + ((lane >> 4) << 3)) * ND_STRIDE
                       + (((lane >> 3) & 1) << 4);
    const uint32_t bY  = sb + OFF_YT + (uint32_t)(wn2 * 64) * YT_STRIDE
                       + ((lane & 7) + ((lane >> 4) << 3)) * YT_STRIDE
                       + (((lane >> 3) & 1) << 4);

    // ---- nodes register staging (prefetched one chunk ahead, packed) ----
    const int srow = tid >> 4;                // 0..31
    const int sc16 = tid & 15;                // float4 column group
    uint2 rN[4];
    {
        const float* src = nodes + (size_t)(z * NC + srow) * DK + sc16 * 4;
        #pragma unroll
        for (int i = 0; i < 4; i++) rN[i] = pack_bf4(*(const float4*)(src + i * 64));
    }

    for (int c = z; c < NCHK; c += ZS) {
        // ---- STS nodes chunk from prefetched regs ----
        {
            char* dst = sm + OFF_ND + srow * ND_STRIDE + sc16 * 8;
            #pragma unroll
            for (int i = 0; i < 4; i++) *(uint2*)(dst + i * 128) = rN[i];
        }
        __syncthreads();   // nodes (+W on iter 0) visible

        // ---- GEMM1: yT = W @ nodes^T  (M=128, N=32, K=256) ----
        float aT0[4] = {0,0,0,0}, aT1[4] = {0,0,0,0};
        float aG0[4] = {0,0,0,0}, aG1[4] = {0,0,0,0};
        #pragma unroll
        for (int ks = 0; ks < 16; ks++) {
            uint32_t At[4], Ag[4], Bn[4];
            LDSM_X4(At, aWt + ks * 32);
            LDSM_X4(Ag, aWg + ks * 32);
            LDSM_X4(Bn, bNd + ks * 32);
            MMA_BF16(aT0, At, Bn[0], Bn[1]);
            MMA_BF16(aT1, At, Bn[2], Bn[3]);
            MMA_BF16(aG0, Ag, Bn[0], Bn[1]);
            MMA_BF16(aG1, Ag, Bn[2], Bn[3]);
        }

        // ---- epilogue: y = (t+bt)*sigmoid(g+bg) -> yT smem bf16 ----
        {
            char* r0 = sm + OFF_YT + (wm * 16 + g) * YT_STRIDE + (wn * 16 + 2 * tg) * 2;
            char* r1 = r0 + 8 * YT_STRIDE;
            __nv_bfloat162 h;
            h = __floats2bfloat162_rn((aT0[0] + bt0) * sigm(aG0[0] + bg0),
                                      (aT0[1] + bt0) * sigm(aG0[1] + bg0));
            *(uint32_t*)r0 = *reinterpret_cast<uint32_t*>(&h);
            h = __floats2bfloat162_rn((aT0[2] + bt1) * sigm(aG0[2] + bg1),
                                      (aT0[3] + bt1) * sigm(aG0[3] + bg1));
            *(uint32_t*)r1 = *reinterpret_cast<uint32_t*>(&h);
            h = __floats2bfloat162_rn((aT1[0] + bt0) * sigm(aG1[0] + bg0),
                                      (aT1[1] + bt0) * sigm(aG1[1] + bg0));
            *(uint32_t*)(r0 + 16) = *reinterpret_cast<uint32_t*>(&h);
            h = __floats2bfloat162_rn((aT1[2] + bt1) * sigm(aG1[2] + bg1),
                                      (aT1[3] + bt1) * sigm(aG1[3] + bg1));
            *(uint32_t*)(r1 + 16) = *reinterpret_cast<uint32_t*>(&h);
        }

        // ---- prefetch nodes(c+ZS) into regs: latency hidden under GEMM2 ----
        if (c + ZS < NCHK) {
            const float* src = nodes + (size_t)((c + ZS) * NC + srow) * DK + sc16 * 4;
            #pragma unroll
            for (int i = 0; i < 4; i++) rN[i] = pack_bf4(*(const float4*)(src + i * 64));
        }

        CP_WAIT0();        // mask(c) landed (issued one "phase" earlier)
        __syncthreads();   // yT + mask visible to all warps

        // ---- GEMM2: acc2 += mask @ yT  (warp tile 32b x 64d) ----
        {
            const char* mA = sm + OFF_MK + (wm2 * 32 + g) * MK_STRIDE;
            const char* mB = mA + 8 * MK_STRIDE;
            #pragma unroll
            for (int ks = 0; ks < 2; ks++) {
                const int kk = ks * 16;
                uint32_t A0[4], A1[4];
                A0[0] = cvtm(*(const int2*)(mA + (kk + 2 * tg) * 4));
                A0[1] = cvtm(*(const int2*)(mB + (kk + 2 * tg) * 4));
                A0[2] = cvtm(*(const int2*)(mA + (kk + 8 + 2 * tg) * 4));
                A0[3] = cvtm(*(const int2*)(mB + (kk + 8 + 2 * tg) * 4));
                A1[0] = cvtm(*(const int2*)(mA + 16 * MK_STRIDE + (kk + 2 * tg) * 4));
                A1[1] = cvtm(*(const int2*)(mB + 16 * MK_STRIDE + (kk + 2 * tg) * 4));
                A1[2] = cvtm(*(const int2*)(mA + 16 * MK_STRIDE + (kk + 8 + 2 * tg) * 4));
                A1[3] = cvtm(*(const int2*)(mB + 16 * MK_STRIDE + (kk + 8 + 2 * tg) * 4));
                #pragma unroll
                for (int nf = 0; nf < 4; nf++) {
                    uint32_t Y[4];
                    LDSM_X4(Y, bY + nf * 16 * YT_STRIDE + ks * 32);
                    MMA_BF16(acc2[0][2 * nf],     A0, Y[0], Y[1]);
                    MMA_BF16(acc2[0][2 * nf + 1], A0, Y[2], Y[3]);
                    MMA_BF16(acc2[1][2 * nf],     A1, Y[0], Y[1]);
                    MMA_BF16(acc2[1][2 * nf + 1], A1, Y[2], Y[3]);
                }
            }
        }
        __syncthreads();   // GEMM2 done: mask/yT/nodes smem free

        // ---- issue cp.async mask(c+ZS): lands during next GEMM1 ----
        if (c + ZS < NCHK) {
            const int nn = (c + ZS) * NC;
            #pragma unroll
            for (int i = 0; i < 4; i++) {
                int o = tid + i * 512;
                int row = o >> 3, seg = o & 7;
                CP16(sb + OFF_MK + row * MK_STRIDE + seg * 16,
                     (const char*)(mask + (size_t)row * Nn + nn) + seg * 16);
            }
            CP_COMMIT();
        }
    }

    // ---- drain: atomic-accumulate split-K partials ----
    #pragma unroll
    for (int mf = 0; mf < 2; mf++) {
        const int r = wm2 * 32 + mf * 16 + g;
        #pragma unroll
        for (int j = 0; j < 8; j++) {
            const int cb = d0 + wn2 * 64 + j * 8 + 2 * tg;
            atomicAdd(out + (size_t)r * DK + cb,           acc2[mf][j][0]);
            atomicAdd(out + (size_t)r * DK + cb + 1,       acc2[mf][j][1]);
            atomicAdd(out + (size_t)(r + 8) * DK + cb,     acc2[mf][j][2]);
            atomicAdd(out + (size_t)(r + 8) * DK + cb + 1, acc2[mf][j][3]);
        }
    }
}

__global__ void kzero(float* __restrict__ o, int n) {
    const int i = blockIdx.x * 256 + threadIdx.x;
    if (i < n) o[i] = 0.f;
}

extern "C" void kernel_launch(void* const* d_in, const int* in_sizes, int n_in,
                              void* d_out, int out_size)
{
    const float* nodes = (const float*)d_in[0];
    const int*   mask  = (const int*)  d_in[1];
    const float* Wt    = (const float*)d_in[2];
    const float* bt    = (const float*)d_in[3];
    const float* Wg    = (const float*)d_in[4];
    const float* bg    = (const float*)d_in[5];
    float* out = (float*)d_out;

    const int Nn = in_sizes[0] / DK;   // 200000

    cudaFuncSetAttribute(fused_agg, cudaFuncAttributeMaxDynamicSharedMemorySize, SMEM_TOTAL);

    kzero<<<(out_size + 255) / 256, 256>>>(out, out_size);
    fused_agg<<<dim3(ZS, 2), 512, SMEM_TOTAL>>>(nodes, mask, Wt, bt, Wg, bg, out, Nn);
}